// round 5
// baseline (speedup 1.0000x reference)
#include <cuda_runtime.h>
#include <cstdint>

// Problem constants (fixed by setup_inputs)
#define N_NODES 8192
#define IN_DIM  256
#define OUT_DIM 64
#define SLOPE   0.2f

#define GEMM_BLOCKS 128
#define LCAP 256          // per-row neighbor cap (Binomial mean 82, sd 9 -> 19 sigma)

// Scratch (allocation-free rule: __device__ globals)
__device__ float g_proj[N_NODES * OUT_DIM];   // 2 MB
__device__ float g_si[N_NODES];
__device__ float g_sj[N_NODES];
__device__ int   g_done;                      // reset to 0 by memset each launch

// ---------------------------------------------------------------------------
// GEMM tile params
// ---------------------------------------------------------------------------
#define GM_BM 64
#define GM_BK 32
#define AS_LD 68   // 64 + 4 padding

__device__ __forceinline__ float leaky(float x) {
    return x > 0.0f ? x : SLOPE * x;
}

__device__ __forceinline__ float block_reduce(float v, float* s8, bool do_max)
{
    int lane = threadIdx.x & 31;
    int warp = threadIdx.x >> 5;
    #pragma unroll
    for (int o = 16; o > 0; o >>= 1) {
        float t = __shfl_xor_sync(0xffffffffu, v, o);
        v = do_max ? fmaxf(v, t) : (v + t);
    }
    __syncthreads();
    if (lane == 0) s8[warp] = v;
    __syncthreads();
    if (threadIdx.x == 0) {
        float r = s8[0];
        #pragma unroll
        for (int w = 1; w < 8; w++)
            r = do_max ? fmaxf(r, s8[w]) : (r + s8[w]);
        s8[0] = r;
    }
    __syncthreads();
    return s8[0];
}

// ---------------------------------------------------------------------------
// ONE fused kernel.
//   blocks [0, 128):       proj = X@W + s_i/s_j epilogue, then signal g_done.
//   blocks [128, 128+8192): scan own adjacency row (DRAM-bound, independent of
//                           GEMM), spin until g_done==128, then softmax+gather.
// GEMM blocks are the lowest block indices -> scheduled in wave 1 -> always
// make progress -> the spin cannot deadlock. Scan blocks stream adjacency
// BEFORE spinning, so DRAM stays saturated while GEMM completes.
// ---------------------------------------------------------------------------
__global__ __launch_bounds__(256) void fused_gat_kernel(
    const float* __restrict__ X, const float* __restrict__ W,
    const float* __restrict__ a, const unsigned* __restrict__ adj,
    float* __restrict__ out)
{
    __shared__ float s_smem[2 * GM_BK * AS_LD];          // GEMM As (reused below)
    __shared__ float Bs[2][GM_BK][OUT_DIM];              // GEMM Bs
    __shared__ float a_s[2 * OUT_DIM];

    const int tid  = threadIdx.x;
    const int lane = tid & 31;
    const int warp = tid >> 5;

    if (blockIdx.x >= GEMM_BLOCKS) {
        // =============== scan + softmax + gather path ===============
        // overlay scan smem onto the (unused here) GEMM buffers
        unsigned short* s_id  = (unsigned short*)s_smem;                 // LCAP u16
        float*          s_w   = (float*)(s_id + LCAP);                   // LCAP f32
        float*          s_acc = s_w + LCAP;                              // 4*64 f32
        float*          s_red = s_acc + 4 * OUT_DIM;                     // 8
        int*            s_wc  = (int*)(s_red + 8);                       // 8

        const int row = blockIdx.x - GEMM_BLOCKS;
        const uint4* arow4 = (const uint4*)(adj + (size_t)row * N_NODES); // 2048 uint4

        // ---- stream the row: 8 independent LDG.128 per thread ----
        uint4 v[8];
        #pragma unroll
        for (int i = 0; i < 8; i++)
            v[i] = arow4[warp * 256 + i * 32 + lane];

        unsigned mk[8][4];
        int wcnt = 0;
        #pragma unroll
        for (int i = 0; i < 8; i++) {
            mk[i][0] = __ballot_sync(0xffffffffu, v[i].x != 0u);
            mk[i][1] = __ballot_sync(0xffffffffu, v[i].y != 0u);
            mk[i][2] = __ballot_sync(0xffffffffu, v[i].z != 0u);
            mk[i][3] = __ballot_sync(0xffffffffu, v[i].w != 0u);
            wcnt += __popc(mk[i][0]) + __popc(mk[i][1])
                  + __popc(mk[i][2]) + __popc(mk[i][3]);
        }

        if (lane == 0) s_wc[warp] = wcnt;
        __syncthreads();
        int base = 0, cnt = 0;
        #pragma unroll
        for (int w = 0; w < 8; w++) {
            int c = s_wc[w];
            if (w < warp) base += c;
            cnt += c;
        }

        if (cnt <= LCAP) {
            int off = base;
            const unsigned lt = (1u << lane) - 1u;
            #pragma unroll
            for (int i = 0; i < 8; i++) {
                #pragma unroll
                for (int c = 0; c < 4; c++) {
                    unsigned m = mk[i][c];
                    if (m & (1u << lane)) {
                        int pos = off + __popc(m & lt);
                        s_id[pos] = (unsigned short)(warp * 1024 + i * 128 + 4 * lane + c);
                    }
                    off += __popc(m);
                }
            }
        }
        __syncthreads();

        // ---- wait for GEMM completion (proj, s_i, s_j valid after) ----
        if (tid == 0) {
            while (*(volatile int*)&g_done < GEMM_BLOCKS) { }
        }
        __syncthreads();
        __threadfence();

        const float si_r = g_si[row];
        const int   g    = tid >> 6;      // group 0..3
        const int   d    = tid & 63;      // output dim

        if (cnt > 0 && cnt <= LCAP) {
            // ---------------- fast path ----------------
            float lm = -INFINITY;
            float e0 = 0.0f;
            if (tid < cnt) {
                e0 = leaky(si_r + g_sj[s_id[tid]]);
                lm = e0;
            }
            float m = block_reduce(lm, s_red, true);

            float ls = 0.0f;
            if (tid < cnt) {
                float w = __expf(e0 - m);
                s_w[tid] = w;
                ls = w;
            }
            float denom = block_reduce(ls, s_red, false);

            float acc = 0.0f;
            #pragma unroll 4
            for (int k = g; k < cnt; k += 4)
                acc += s_w[k] * g_proj[(size_t)s_id[k] * OUT_DIM + d];
            s_acc[g * OUT_DIM + d] = acc;
            __syncthreads();
            if (g == 0) {
                float tot = s_acc[0 * OUT_DIM + d] + s_acc[1 * OUT_DIM + d]
                          + s_acc[2 * OUT_DIM + d] + s_acc[3 * OUT_DIM + d];
                out[(size_t)row * OUT_DIM + d] = tot / denom;
            }
            return;
        }

        if (cnt == 0) {
            // softmax over all-NEG_BIG row is uniform: out = mean(proj)
            float acc = 0.0f;
            for (int j = g; j < N_NODES; j += 4)
                acc += g_proj[(size_t)j * OUT_DIM + d];
            s_acc[g * OUT_DIM + d] = acc;
            __syncthreads();
            if (g == 0) {
                float tot = s_acc[0 * OUT_DIM + d] + s_acc[1 * OUT_DIM + d]
                          + s_acc[2 * OUT_DIM + d] + s_acc[3 * OUT_DIM + d];
                out[(size_t)row * OUT_DIM + d] = tot * (1.0f / (float)N_NODES);
            }
            return;
        }

        // ---- overflow fallback (cnt > LCAP, ~never): direct rescan ----
        const unsigned* arow = adj + (size_t)row * N_NODES;
        float lm = -INFINITY;
        for (int j = tid; j < N_NODES; j += 256)
            if (arow[j]) lm = fmaxf(lm, leaky(si_r + g_sj[j]));
        float m = block_reduce(lm, s_red, true);

        float ls = 0.0f;
        for (int j = tid; j < N_NODES; j += 256)
            if (arow[j]) ls += __expf(leaky(si_r + g_sj[j]) - m);
        float denom = block_reduce(ls, s_red, false);

        float acc = 0.0f;
        for (int j = g; j < N_NODES; j += 4)
            if (arow[j]) {
                float w = __expf(leaky(si_r + g_sj[j]) - m);
                acc += w * g_proj[(size_t)j * OUT_DIM + d];
            }
        s_acc[g * OUT_DIM + d] = acc;
        __syncthreads();
        if (g == 0) {
            float tot = s_acc[0 * OUT_DIM + d] + s_acc[1 * OUT_DIM + d]
                      + s_acc[2 * OUT_DIM + d] + s_acc[3 * OUT_DIM + d];
            out[(size_t)row * OUT_DIM + d] = tot / denom;
        }
        return;
    }

    // ======================= GEMM + s epilogue path =======================
    float* As = s_smem;   // [2][GM_BK * AS_LD]

    const int block_row = blockIdx.x * GM_BM;
    const int trow = tid >> 4;
    const int tcol = tid & 15;

    if (tid < 128) a_s[tid] = a[tid];

    const int a_r0 = tid >> 3;
    const int a_c4 = tid & 7;
    const int a_r1 = (tid + 256) >> 3;
    const int b_r0 = tid >> 4;
    const int b_c4 = tid & 15;
    const int b_r1 = (tid + 256) >> 4;

    float4 rA0, rA1, rB0, rB1;

    auto load_tiles = [&](int k0) {
        rA0 = *(const float4*)(X + (size_t)(block_row + a_r0) * IN_DIM + k0 + a_c4 * 4);
        rA1 = *(const float4*)(X + (size_t)(block_row + a_r1) * IN_DIM + k0 + a_c4 * 4);
        rB0 = *(const float4*)(W + (size_t)(k0 + b_r0) * OUT_DIM + b_c4 * 4);
        rB1 = *(const float4*)(W + (size_t)(k0 + b_r1) * OUT_DIM + b_c4 * 4);
    };
    auto store_tiles = [&](int buf) {
        float* Ab = As + buf * (GM_BK * AS_LD);
        Ab[(a_c4 * 4 + 0) * AS_LD + a_r0] = rA0.x;
        Ab[(a_c4 * 4 + 1) * AS_LD + a_r0] = rA0.y;
        Ab[(a_c4 * 4 + 2) * AS_LD + a_r0] = rA0.z;
        Ab[(a_c4 * 4 + 3) * AS_LD + a_r0] = rA0.w;
        Ab[(a_c4 * 4 + 0) * AS_LD + a_r1] = rA1.x;
        Ab[(a_c4 * 4 + 1) * AS_LD + a_r1] = rA1.y;
        Ab[(a_c4 * 4 + 2) * AS_LD + a_r1] = rA1.z;
        Ab[(a_c4 * 4 + 3) * AS_LD + a_r1] = rA1.w;
        *(float4*)&Bs[buf][b_r0][b_c4 * 4] = rB0;
        *(float4*)&Bs[buf][b_r1][b_c4 * 4] = rB1;
    };

    float acc[4][4];
    #pragma unroll
    for (int i = 0; i < 4; i++)
        #pragma unroll
        for (int j = 0; j < 4; j++) acc[i][j] = 0.0f;

    load_tiles(0);
    store_tiles(0);
    __syncthreads();

    const int NT = IN_DIM / GM_BK;
    for (int t = 0; t < NT; t++) {
        int buf = t & 1;
        if (t + 1 < NT) load_tiles((t + 1) * GM_BK);

        const float* Ab = As + buf * (GM_BK * AS_LD);
        #pragma unroll
        for (int k = 0; k < GM_BK; k++) {
            float4 av = *(const float4*)&Ab[k * AS_LD + trow * 4];
            float4 bv = *(const float4*)&Bs[buf][k][tcol * 4];
            float aa[4] = {av.x, av.y, av.z, av.w};
            float bb[4] = {bv.x, bv.y, bv.z, bv.w};
            #pragma unroll
            for (int i = 0; i < 4; i++)
                #pragma unroll
                for (int j = 0; j < 4; j++)
                    acc[i][j] = fmaf(aa[i], bb[j], acc[i][j]);
        }
        if (t + 1 < NT) store_tiles(buf ^ 1);
        __syncthreads();
    }

    #pragma unroll
    for (int i = 0; i < 4; i++) {
        int row = block_row + trow * 4 + i;
        float4 vv = make_float4(acc[i][0], acc[i][1], acc[i][2], acc[i][3]);
        *(float4*)(g_proj + (size_t)row * OUT_DIM + tcol * 4) = vv;

        float q0 = acc[i][0] * a_s[tcol * 4 + 0] + acc[i][1] * a_s[tcol * 4 + 1]
                 + acc[i][2] * a_s[tcol * 4 + 2] + acc[i][3] * a_s[tcol * 4 + 3];
        float q1 = acc[i][0] * a_s[64 + tcol * 4 + 0] + acc[i][1] * a_s[64 + tcol * 4 + 1]
                 + acc[i][2] * a_s[64 + tcol * 4 + 2] + acc[i][3] * a_s[64 + tcol * 4 + 3];
        #pragma unroll
        for (int o = 8; o > 0; o >>= 1) {
            q0 += __shfl_down_sync(0xffffffffu, q0, o, 16);
            q1 += __shfl_down_sync(0xffffffffu, q1, o, 16);
        }
        if (tcol == 0) { g_si[row] = q0; g_sj[row] = q1; }
    }

    // ---- signal completion (release) ----
    __syncthreads();
    if (tid == 0) {
        __threadfence();
        atomicAdd(&g_done, 1);
    }
}

// ---------------------------------------------------------------------------
// Launch
// ---------------------------------------------------------------------------
extern "C" void kernel_launch(void* const* d_in, const int* in_sizes, int n_in,
                              void* d_out, int out_size)
{
    const float*    X   = (const float*)d_in[0];
    const unsigned* adj = (const unsigned*)d_in[1];   // bool widened to 32-bit
    const float*    W   = (const float*)d_in[2];
    const float*    a   = (const float*)d_in[3];
    float*          out = (float*)d_out;

    void* done_addr = nullptr;
    cudaGetSymbolAddress(&done_addr, g_done);
    cudaMemsetAsync(done_addr, 0, sizeof(int));      // capture-legal reset

    fused_gat_kernel<<<GEMM_BLOCKS + N_NODES, 256>>>(X, W, a, adj, out);
}